// round 1
// baseline (speedup 1.0000x reference)
#include <cuda_runtime.h>
#include <math.h>

// Problem constants
#define BB   4
#define CH   32
#define GCH  384
#define HH   224
#define WW   224
#define HW   50176            // 224*224
#define NPLANE 6422528        // 4*32*224*224 (one spn tensor)
#define N4     1605632        // NPLANE/4
#define WT   8                // scan tile width (steps per SMEM tile)
#define SSTR 233              // padded SMEM row stride (bank-conflict friendly)

// Scratch (static device globals; no allocation allowed)
__device__ __align__(16) float g_y32[NPLANE];        // conv1 output
__device__ __align__(16) float g_dir[4 * NPLANE];    // 4 directional outputs
__device__ __align__(16) float g_s1[NPLANE];         // spn pass 1 result
__device__ __align__(16) float g_s2[NPLANE];         // spn pass 2 result

// ---------------------------------------------------------------------------
// conv1: y [4,2,224,224] -> g_y32 [4,32,224,224], 3x3 same, no bias
// grid: (b*224+h) = 896 blocks, 224 threads (one per w)
// ---------------------------------------------------------------------------
__global__ void __launch_bounds__(224) conv1_kernel(
    const float* __restrict__ y, const float* __restrict__ w3)
{
    int b = blockIdx.x / HH;
    int h = blockIdx.x % HH;
    int tid = threadIdx.x;

    __shared__ float si[2][3][WW + 2];   // padded cols
    __shared__ float sw[32 * 2 * 9];

    for (int i = tid; i < 576; i += 224) sw[i] = w3[i];

    #pragma unroll
    for (int ic = 0; ic < 2; ic++) {
        #pragma unroll
        for (int r = 0; r < 3; r++) {
            int hh = h + r - 1;
            float v = (hh >= 0 && hh < HH)
                        ? y[((size_t)(b * 2 + ic) * HH + hh) * WW + tid] : 0.f;
            si[ic][r][tid + 1] = v;
            if (tid < 2) si[ic][r][tid * (WW + 1)] = 0.f;  // cols 0 and 225
        }
    }
    __syncthreads();

    float v[18];
    #pragma unroll
    for (int ic = 0; ic < 2; ic++)
        #pragma unroll
        for (int r = 0; r < 3; r++)
            #pragma unroll
            for (int dx = 0; dx < 3; dx++)
                v[ic * 9 + r * 3 + dx] = si[ic][r][tid + dx];

    for (int oc = 0; oc < 32; oc++) {
        float acc = 0.f;
        #pragma unroll
        for (int k = 0; k < 18; k++) acc = fmaf(v[k], sw[oc * 18 + k], acc);
        g_y32[((size_t)(b * 32 + oc) * HH + h) * WW + tid] = acc;
    }
}

// ---------------------------------------------------------------------------
// Propagation: one CTA per (direction, b, c) plane. 224 threads = vector dim.
// Serial scan of 224 steps; tiles of WT=8 steps staged in SMEM (coalesced).
// dir map: 0=lr(hor,fwd) 1=rl(vert,rev) 2=du(vert,fwd) 3=ud(hor,rev)
// pass==0: x = g_y32 ; pass==1: x = g_s1.  Output -> g_dir[d].
// ---------------------------------------------------------------------------
__global__ void __launch_bounds__(224) prop_kernel(
    const float* __restrict__ gates, int pass)
{
    int pid = blockIdx.x;           // 0..511
    int d  = pid >> 7;
    int bc = pid & 127;
    int b  = bc >> 5;
    int c  = bc & 31;
    bool hor = (d == 0 || d == 3);
    bool rev = (d == 1 || d == 3);

    const float* xin = (pass == 0) ? g_y32 : g_s1;
    const float* xp  = xin + (size_t)bc * HW;
    float*       op  = g_dir + (size_t)(d * 128 + bc) * HW;
    const float* g1p = gates + ((size_t)b * GCH + d * 96 + c) * HW;
    const float* g2p = g1p + (size_t)32 * HW;
    const float* g3p = g1p + (size_t)64 * HW;

    __shared__ float tx[WT * SSTR], t1[WT * SSTR], t2[WT * SSTR],
                     t3[WT * SSTR], to[WT * SSTR];
    __shared__ float hb[2][WW + 2];

    int tid = threadIdx.x;
    for (int i = tid; i < 2 * (WW + 2); i += 224) ((float*)hb)[i] = 0.f;

    float hreg = 0.f;

    for (int tb = 0; tb < HH / WT; tb++) {
        int t0 = tb * WT;

        // ---- load x,g1,g2,g3 tiles (coalesced) ----
        if (hor) {
            #pragma unroll
            for (int i = 0; i < WT; i++) {
                int idx = i * 224 + tid;
                int s = idx >> 3, j = idx & 7;
                int tg = rev ? (223 - t0 - j) : (t0 + j);
                int off = s * WW + tg;
                int m = j * SSTR + s;
                tx[m] = xp[off];  t1[m] = g1p[off];
                t2[m] = g2p[off]; t3[m] = g3p[off];
            }
        } else {
            #pragma unroll
            for (int i = 0; i < WT; i++) {
                int tg = rev ? (223 - t0 - i) : (t0 + i);
                int off = tg * WW + tid;
                int m = i * SSTR + tid;
                tx[m] = xp[off];  t1[m] = g1p[off];
                t2[m] = g2p[off]; t3[m] = g3p[off];
            }
        }
        __syncthreads();

        // ---- serial scan over WT steps ----
        #pragma unroll
        for (int j = 0; j < WT; j++) {
            int t = t0 + j;
            const float* hp = hb[t & 1];
            float*       hc = hb[(t & 1) ^ 1];
            int m = j * SSTR + tid;
            float xv = tx[m], a1 = t1[m], a2 = t2[m], a3 = t3[m];
            float sa = fabsf(a1) + fabsf(a2) + fabsf(a3);
            float inv = __fdividef(1.0f, fmaxf(sa, 1.0f));
            a1 *= inv; a2 *= inv; a3 *= inv;
            float hn = (1.0f - a1 - a2 - a3) * xv
                     + a1 * hp[tid] + a2 * hreg + a3 * hp[tid + 2];
            hc[tid + 1] = hn;
            to[m] = hn;
            hreg = hn;
            __syncthreads();
        }

        // ---- flush output tile (coalesced stores) ----
        if (hor) {
            #pragma unroll
            for (int i = 0; i < WT; i++) {
                int idx = i * 224 + tid;
                int s = idx >> 3, j = idx & 7;
                int tg = rev ? (223 - t0 - j) : (t0 + j);
                op[s * WW + tg] = to[j * SSTR + s];
            }
        } else {
            #pragma unroll
            for (int i = 0; i < WT; i++) {
                int tg = rev ? (223 - t0 - i) : (t0 + i);
                op[tg * WW + tid] = to[i * SSTR + tid];
            }
        }
        // no extra sync needed: next tile's load-sync orders flush reads
        // before the next inner loop rewrites `to`.
    }
}

// ---------------------------------------------------------------------------
// max over 4 direction buffers -> g_s1 (pass 0) or g_s2 (pass 1)
// ---------------------------------------------------------------------------
__global__ void max_kernel(int pass)
{
    int i = blockIdx.x * blockDim.x + threadIdx.x;
    if (i >= N4) return;
    const float4* d0 = (const float4*)g_dir;
    float4 a = d0[i];
    float4 b = d0[i + N4];
    float4 c = d0[i + 2 * N4];
    float4 e = d0[i + 3 * N4];
    float4 r;
    r.x = fmaxf(fmaxf(a.x, b.x), fmaxf(c.x, e.x));
    r.y = fmaxf(fmaxf(a.y, b.y), fmaxf(c.y, e.y));
    r.z = fmaxf(fmaxf(a.z, b.z), fmaxf(c.z, e.z));
    r.w = fmaxf(fmaxf(a.w, b.w), fmaxf(c.w, e.w));
    float4* dst = (float4*)(pass ? g_s2 : g_s1);
    dst[i] = r;
}

// ---------------------------------------------------------------------------
// conv2 (32->2, 3x3 same) + log_softmax over channel dim (2)
// grid: (b*224+h) = 896 blocks, 224 threads
// ---------------------------------------------------------------------------
__global__ void __launch_bounds__(224) conv2_ls_kernel(
    const float* __restrict__ w4, float* __restrict__ out)
{
    int b = blockIdx.x / HH;
    int h = blockIdx.x % HH;
    int tid = threadIdx.x;

    __shared__ float si[16][3][WW + 2];     // 16 ic chunk
    __shared__ float sw[2 * 32 * 9];

    for (int i = tid; i < 576; i += 224) sw[i] = w4[i];

    float acc0 = 0.f, acc1 = 0.f;

    for (int chunk = 0; chunk < 2; chunk++) {
        __syncthreads();
        for (int icl = 0; icl < 16; icl++) {
            int ic = chunk * 16 + icl;
            #pragma unroll
            for (int r = 0; r < 3; r++) {
                int hh = h + r - 1;
                float v = (hh >= 0 && hh < HH)
                    ? g_s2[((size_t)(b * 32 + ic) * HH + hh) * WW + tid] : 0.f;
                si[icl][r][tid + 1] = v;
                if (tid < 2) si[icl][r][tid * (WW + 1)] = 0.f;
            }
        }
        __syncthreads();
        for (int icl = 0; icl < 16; icl++) {
            int ic = chunk * 16 + icl;
            #pragma unroll
            for (int r = 0; r < 3; r++)
                #pragma unroll
                for (int dx = 0; dx < 3; dx++) {
                    float v = si[icl][r][tid + dx];
                    int k = ic * 9 + r * 3 + dx;
                    acc0 = fmaf(v, sw[k], acc0);
                    acc1 = fmaf(v, sw[288 + k], acc1);
                }
        }
    }

    // log_softmax over {acc0, acc1}
    float m  = fmaxf(acc0, acc1);
    float e0 = __expf(acc0 - m), e1 = __expf(acc1 - m);
    float lse = m + __logf(e0 + e1);
    size_t o = ((size_t)b * 2 * HH + h) * WW + tid;
    out[o]          = acc0 - lse;
    out[o + HW]     = acc1 - lse;
}

// ---------------------------------------------------------------------------
extern "C" void kernel_launch(void* const* d_in, const int* in_sizes, int n_in,
                              void* d_out, int out_size)
{
    const float* gates = (const float*)d_in[0];  // [4,384,224,224]
    const float* y     = (const float*)d_in[1];  // [4,2,224,224]
    const float* w3    = (const float*)d_in[2];  // [32,2,3,3]
    const float* w4    = (const float*)d_in[3];  // [2,32,3,3]
    float* out = (float*)d_out;                  // [4,2,224,224]

    (void)in_sizes; (void)n_in; (void)out_size;

    conv1_kernel<<<BB * HH, 224>>>(y, w3);
    prop_kernel<<<512, 224>>>(gates, 0);
    max_kernel<<<(N4 + 255) / 256, 256>>>(0);
    prop_kernel<<<512, 224>>>(gates, 1);
    max_kernel<<<(N4 + 255) / 256, 256>>>(1);
    conv2_ls_kernel<<<BB * HH, 224>>>(w4, out);
}